// round 15
// baseline (speedup 1.0000x reference)
#include <cuda_runtime.h>

// ---------------------------------------------------------------------------
// EquivGNNEncoder on GB300, v11 = v8 + reduction-dim packed dense matvecs.
// v8's dense phases spent ~half their issue slots on splat MOVs (mov.b64
// {r,r} = 2 MOVs). Weights are pre-interleaved by k_pack as (W[2j][w],
// W[2j+1][w]) u64 pairs with all scale constants folded in; inputs are read
// as contiguous pairs; accumulators hold (even,odd) partials folded by one
// FADD per output. Zero splats in dense code.
// ---------------------------------------------------------------------------

#define MAXN (1 << 17)
#define MAXB 4096
#define PACKN (1024 + 3 * 3584)

typedef unsigned long long u64;

__device__ float g_hg[MAXB * 80];
__device__ float g_wpack[PACKN];   // [Ws2n' | layer0' | layer1' | layer2']

__device__ __forceinline__ void cpa16(void* s, const void* g) {
    unsigned sa = (unsigned)__cvta_generic_to_shared(s);
    asm volatile("cp.async.cg.shared.global [%0], [%1], 16;\n" :: "r"(sa), "l"(g));
}
__device__ __forceinline__ void cpa_commit() {
    asm volatile("cp.async.commit_group;\n");
}
template<int N> __device__ __forceinline__ void cpa_wait() {
    asm volatile("cp.async.wait_group %0;\n" :: "n"(N) : "memory");
}

__device__ __forceinline__ u64 pk2(float lo, float hi) {
    u64 r; asm("mov.b64 %0, {%1, %2};" : "=l"(r) : "f"(lo), "f"(hi)); return r;
}
__device__ __forceinline__ u64 splat2(float v) { return pk2(v, v); }
__device__ __forceinline__ void upk2(u64 v, float& lo, float& hi) {
    asm("mov.b64 {%0, %1}, %2;" : "=f"(lo), "=f"(hi) : "l"(v));
}
__device__ __forceinline__ float fold2(u64 v) {
    float lo, hi; upk2(v, lo, hi); return lo + hi;
}
__device__ __forceinline__ void ffma2(u64& d, u64 a, u64 b) {
    asm("fma.rn.f32x2 %0, %1, %2, %0;" : "+l"(d) : "l"(a), "l"(b));
}
__device__ __forceinline__ void fadd2(u64& d, u64 a) {
    asm("add.rn.f32x2 %0, %1, %0;" : "+l"(d) : "l"(a));
}

// pack + pre-scale weights, reduction-interleaved:
// dst float idx (within a matrix of U rows, Wd cols) = j*(2*Wd) + 2*w + h,
// src = (2j+h)*Wd + w.  Layout in g_wpack identical offsets to kernel sW:
// [Ws2n 1024][per layer: W1 @0 | W2 @1024 | W3 @1536 | W4 @1792 | Ws @2304 | Wv @3328]
__global__ void k_pack(const float* __restrict__ Ws2n,
                       const float* __restrict__ W1, const float* __restrict__ W2,
                       const float* __restrict__ W3, const float* __restrict__ W4,
                       const float* __restrict__ Ws, const float* __restrict__ Wv)
{
    const float INVS3    = 0.5773502691896258f;
    const float C_S      = 0.14433756729740643f;
    const float C_VI     = 0.14433756729740643f;
    const float INV_SQ32 = 0.17677669529663687f;

    int i = blockIdx.x * blockDim.x + threadIdx.x;
    if (i >= PACKN) return;
    float v;
    if (i < 1024) {                       // Ws2n: U32 Wd32, * 1/sqrt(32)
        int j = i >> 6, rem = i & 63, w = rem >> 1, h = rem & 1;
        v = Ws2n[(2 * j + h) * 32 + w] * INV_SQ32;
    } else {
        int e = i - 1024;
        int l = e / 3584, k = e - l * 3584;
        if (k < 1024) {                   // W1: U32 Wd32, * C_S
            int j = k >> 6, rem = k & 63, w = rem >> 1, h = rem & 1;
            v = W1[l * 1024 + (2 * j + h) * 32 + w] * C_S;
        } else if (k < 1536) {            // W2: U32 Wd16, * C_VI
            int q = k - 1024;
            int j = q >> 5, rem = q & 31, w = rem >> 1, h = rem & 1;
            v = W2[l * 512 + (2 * j + h) * 16 + w] * C_VI;
        } else if (k < 1792) {            // W3: U16 Wd16, * C_VI
            int q = k - 1536;
            int j = q >> 5, rem = q & 31, w = rem >> 1, h = rem & 1;
            v = W3[l * 256 + (2 * j + h) * 16 + w] * C_VI;
        } else if (k < 2304) {            // W4: U16 Wd32, * C_S*INVS3
            int q = k - 1792;
            int j = q >> 6, rem = q & 63, w = rem >> 1, h = rem & 1;
            v = W4[l * 512 + (2 * j + h) * 32 + w] * (C_S * INVS3);
        } else if (k < 3328) {            // Ws: U32 Wd32, * 1/sqrt(32)
            int q = k - 2304;
            int j = q >> 6, rem = q & 63, w = rem >> 1, h = rem & 1;
            v = Ws[l * 1024 + (2 * j + h) * 32 + w] * INV_SQ32;
        } else {                          // Wv: U16 Wd16, * 0.25
            int q = k - 3328;
            int j = q >> 5, rem = q & 31, w = rem >> 1, h = rem & 1;
            v = Wv[l * 256 + (2 * j + h) * 16 + w] * 0.25f;
        }
    }
    g_wpack[i] = v;
}

// smem float offsets (total 14272 floats = 57088 B -> 4 CTAs/SM):
#define SPOS 0        // pos float4 [32]        (128)
#define SS   128      // [n] stride 36          (1152)
#define SV4  1280     // float4 [n*17+w]        (2176)
#define SSB  3456     // S_bar [n] stride 36    (1152)
#define SR   4608     // r [n] stride 20        (640)
#define SVB  5248     // Vbar [(n*3+i)]*20      (1920)
#define SP   7168     // p [(n*3+i)]*36         (3456)
#define SAS  7168     // alias over sP          (1152)
#define SAV  8320     // alias over sP          (1920)
#define SW   10624    // 3584 packed
#define SADJ 14208
#define SZI  14240
#define SMEM_GNN (14272 * 4)

// packed matvec helpers: in32/in16 = pointer to contiguous input row,
// wp = ulonglong2 weight base. Wd32: 4 outputs (w=4q8..+3); Wd16: 2 outputs.
__device__ __forceinline__ void mv32x32(const ulonglong2* ip,
                                        const ulonglong2* wp, int q8,
                                        u64& a0, u64& a1, u64& a2, u64& a3)
{
    #pragma unroll
    for (int k = 0; k < 8; ++k) {
        ulonglong2 in2 = ip[k];
        ulonglong2 wA = wp[(2 * k) * 16 + 2 * q8];
        ulonglong2 wB = wp[(2 * k) * 16 + 2 * q8 + 1];
        ffma2(a0, in2.x, wA.x); ffma2(a1, in2.x, wA.y);
        ffma2(a2, in2.x, wB.x); ffma2(a3, in2.x, wB.y);
        wA = wp[(2 * k + 1) * 16 + 2 * q8];
        wB = wp[(2 * k + 1) * 16 + 2 * q8 + 1];
        ffma2(a0, in2.y, wA.x); ffma2(a1, in2.y, wA.y);
        ffma2(a2, in2.y, wB.x); ffma2(a3, in2.y, wB.y);
    }
}
__device__ __forceinline__ void mv16x32(const ulonglong2* ip,
                                        const ulonglong2* wp, int q8,
                                        u64& a0, u64& a1, u64& a2, u64& a3)
{
    #pragma unroll
    for (int k = 0; k < 4; ++k) {
        ulonglong2 in2 = ip[k];
        ulonglong2 wA = wp[(2 * k) * 16 + 2 * q8];
        ulonglong2 wB = wp[(2 * k) * 16 + 2 * q8 + 1];
        ffma2(a0, in2.x, wA.x); ffma2(a1, in2.x, wA.y);
        ffma2(a2, in2.x, wB.x); ffma2(a3, in2.x, wB.y);
        wA = wp[(2 * k + 1) * 16 + 2 * q8];
        wB = wp[(2 * k + 1) * 16 + 2 * q8 + 1];
        ffma2(a0, in2.y, wA.x); ffma2(a1, in2.y, wA.y);
        ffma2(a2, in2.y, wB.x); ffma2(a3, in2.y, wB.y);
    }
}
__device__ __forceinline__ void mv32x16(const ulonglong2* ip,
                                        const ulonglong2* wp, int q8,
                                        u64& b0, u64& b1)
{
    #pragma unroll
    for (int k = 0; k < 8; ++k) {
        ulonglong2 in2 = ip[k];
        ulonglong2 wA = wp[(2 * k) * 8 + q8];
        ffma2(b0, in2.x, wA.x); ffma2(b1, in2.x, wA.y);
        ulonglong2 wB = wp[(2 * k + 1) * 8 + q8];
        ffma2(b0, in2.y, wB.x); ffma2(b1, in2.y, wB.y);
    }
}
__device__ __forceinline__ void mv16x16(const ulonglong2* ip,
                                        const ulonglong2* wp, int q8,
                                        u64& b0, u64& b1)
{
    #pragma unroll
    for (int k = 0; k < 4; ++k) {
        ulonglong2 in2 = ip[k];
        ulonglong2 wA = wp[(2 * k) * 8 + q8];
        ffma2(b0, in2.x, wA.x); ffma2(b1, in2.x, wA.y);
        ulonglong2 wB = wp[(2 * k + 1) * 8 + q8];
        ffma2(b0, in2.y, wB.x); ffma2(b1, in2.y, wB.y);
    }
}

__global__ void __launch_bounds__(256, 4) k_gnn(
    const float* __restrict__ pos, const int* __restrict__ z,
    const float* __restrict__ emb)
{
    extern __shared__ float sm[];
    float* sW = sm + SW;
    unsigned* sAdj = (unsigned*)(sm + SADJ);
    int*      sZi  = (int*)(sm + SZI);

    const int g    = blockIdx.x;
    const int tid  = threadIdx.x;
    const int n8   = tid >> 3;     // node (0..31)
    const int q8   = tid & 7;      // slice
    const int warp = tid >> 5;
    const int lane = tid & 31;

    const float SQRT3 = 1.7320508075688772f;
    const float R2    = 25.0f;

    // ---- stage packed Ws2n; load statics ----
    cpa16((float4*)sW + tid, (const float4*)g_wpack + tid);
    cpa_commit();
    if (tid < 96) {
        int n = tid / 3, c = tid - n * 3;
        sm[SPOS + n * 4 + c] = pos[g * 96 + tid];
    }
    if (tid < 32) {
        sm[SPOS + tid * 4 + 3] = 0.f;
        sZi[tid] = z[g * 32 + tid];
    }
    __syncthreads();

    // ---- adjacency from pos (bit-identical to reference predicate) ----
    {
        const float4* pos4 = (const float4*)(sm + SPOS);
        float4 pm = pos4[lane];
        #pragma unroll
        for (int k = 0; k < 4; ++k) {
            int n = warp * 4 + k;
            float4 pn = pos4[n];
            float dx = __fsub_rn(pn.x, pm.x);
            float dy = __fsub_rn(pn.y, pm.y);
            float dz = __fsub_rn(pn.z, pm.z);
            float d2 = __fadd_rn(__fadd_rn(__fmul_rn(dx, dx), __fmul_rn(dy, dy)),
                                 __fmul_rn(dz, dz));
            unsigned msk = __ballot_sync(0xffffffffu, d2 <= R2 && d2 > 0.f);
            if (lane == 0) sAdj[n] = msk;
        }
    }

    // ---- emb gather, v = 0 ----
    {
        const float4* emb4 = (const float4*)emb;
        ((float4*)(sm + SSB + n8 * 36))[q8] = emb4[sZi[n8] * 8 + q8];
        float4 z4 = {0.f, 0.f, 0.f, 0.f};
        for (int i = tid; i < 544; i += 256) ((float4*)(sm + SV4))[i] = z4;
    }
    cpa_wait<0>();
    __syncthreads();

    // ---- initial s = emb @ Ws2n' (scale folded) ----
    {
        u64 a0 = 0, a1 = 0, a2 = 0, a3 = 0;
        mv32x32((const ulonglong2*)(sm + SSB + n8 * 36),
                (const ulonglong2*)sW, q8, a0, a1, a2, a3);
        float4 o;
        o.x = fold2(a0); o.y = fold2(a1); o.z = fold2(a2); o.w = fold2(a3);
        ((float4*)(sm + SS + n8 * 36))[q8] = o;
    }
    __syncthreads();

    // ---- layers ----
    for (int l = 0; l < 3; ++l) {
        // stage packed layer weights (contiguous; overlaps gather)
        {
            float4* wd = (float4*)sW;
            const float4* src = (const float4*)(g_wpack + 1024 + l * 3584);
            cpa16(wd + tid,       src + tid);
            cpa16(wd + 256 + tid, src + 256 + tid);
            cpa16(wd + 512 + tid, src + 512 + tid);
            if (tid < 128) cpa16(wd + 768 + tid, src + 768 + tid);
            cpa_commit();
        }

        // ---- edge gather: warp per 4 nodes, packed (x,y) pairs ----
        {
            int w2 = lane & 15;
            const float4* v4p = (const float4*)(sm + SV4);
            const float4* pos4 = (const float4*)(sm + SPOS);
            for (int k = 0; k < 4; ++k) {
                int n = warp * 4 + k;
                float4 pn = pos4[n];
                unsigned am = sAdj[n];
                float aS = 0.f, aPz = 0.f, aVz = 0.f, aRz = 0.f;
                u64 aPxy = 0, aVxy = 0, aRxy = 0;
                while (am) {
                    int m = __ffs(am) - 1;
                    am &= am - 1;
                    float4 pm = pos4[m];
                    float dx = pn.x - pm.x;
                    float dy = pn.y - pm.y;
                    float dz = pn.z - pm.z;
                    float iv = SQRT3 * rsqrtf(dx * dx + dy * dy + dz * dz);
                    float sx = dx * iv, sy = dy * iv, sz = dz * iv;
                    u64 sxy = pk2(sx, sy);
                    float su = sm[SS + m * 36 + lane];
                    aS += su;
                    ffma2(aPxy, splat2(su), sxy);
                    aPz = fmaf(su, sz, aPz);
                    ulonglong2 vv = *(const ulonglong2*)(v4p + m * 17 + w2);
                    fadd2(aVxy, vv.x);
                    float vz, vpad;
                    upk2(vv.y, vz, vpad);
                    aVz += vz;
                    ffma2(aRxy, vv.x, sxy);
                    aRz = fmaf(vz, sz, aRz);
                }
                float px, py, vxs, vys, rx, ry;
                upk2(aPxy, px, py);
                upk2(aVxy, vxs, vys);
                upk2(aRxy, rx, ry);
                sm[SSB + n * 36 + lane] = aS;
                sm[SP + (n * 3 + 0) * 36 + lane] = px;
                sm[SP + (n * 3 + 1) * 36 + lane] = py;
                sm[SP + (n * 3 + 2) * 36 + lane] = aPz;
                if (lane < 16) {
                    sm[SVB + (n * 3 + 0) * 20 + lane] = vxs;
                    sm[SVB + (n * 3 + 1) * 20 + lane] = vys;
                    sm[SVB + (n * 3 + 2) * 20 + lane] = aVz;
                    sm[SR + n * 20 + lane] = (rx + ry) + aRz;
                }
            }
        }
        cpa_wait<0>();
        __syncthreads();

        // ---- step A part 1: a_v_i = p_i@W2' + Vbar_i@W3' -> registers ----
        float avv[3][2];
        {
            const ulonglong2* w2p = (const ulonglong2*)(sW + 1024);
            const ulonglong2* w3p = (const ulonglong2*)(sW + 1536);
            #pragma unroll
            for (int i = 0; i < 3; ++i) {
                u64 b0 = 0, b1 = 0;
                mv32x16((const ulonglong2*)(sm + SP + (n8 * 3 + i) * 36),
                        w2p, q8, b0, b1);
                mv16x16((const ulonglong2*)(sm + SVB + (n8 * 3 + i) * 20),
                        w3p, q8, b0, b1);
                avv[i][0] = fold2(b0);
                avv[i][1] = fold2(b1);
            }
        }
        __syncthreads();   // all sP/sVb reads done; aliased region writable

        // step A part 2: write a_v; a_s = Sbar@W1' + r@W4' -> SAS
        {
            #pragma unroll
            for (int i = 0; i < 3; ++i)
                *(float2*)(sm + SAV + (n8 * 3 + i) * 20 + q8 * 2) =
                    make_float2(avv[i][0], avv[i][1]);

            u64 a0 = 0, a1 = 0, a2 = 0, a3 = 0;
            mv32x32((const ulonglong2*)(sm + SSB + n8 * 36),
                    (const ulonglong2*)sW, q8, a0, a1, a2, a3);
            mv16x32((const ulonglong2*)(sm + SR + n8 * 20),
                    (const ulonglong2*)(sW + 1792), q8, a0, a1, a2, a3);
            float4 o;
            o.x = fold2(a0); o.y = fold2(a1); o.z = fold2(a2); o.w = fold2(a3);
            ((float4*)(sm + SAS + n8 * 36))[q8] = o;
        }
        __syncthreads();

        // ---- step B: s += relu(a_s@Ws'); v_i += relu(a_v_i@Wv') ----
        {
            u64 a0 = 0, a1 = 0, a2 = 0, a3 = 0;
            mv32x32((const ulonglong2*)(sm + SAS + n8 * 36),
                    (const ulonglong2*)(sW + 2304), q8, a0, a1, a2, a3);
            float4* sp = (float4*)(sm + SS + n8 * 36) + q8;
            float4 sv = *sp;
            sv.x += fmaxf(fold2(a0), 0.f);
            sv.y += fmaxf(fold2(a1), 0.f);
            sv.z += fmaxf(fold2(a2), 0.f);
            sv.w += fmaxf(fold2(a3), 0.f);
            *sp = sv;

            float hv[3][2];
            const ulonglong2* wvp = (const ulonglong2*)(sW + 3328);
            #pragma unroll
            for (int i = 0; i < 3; ++i) {
                u64 b0 = 0, b1 = 0;
                mv16x16((const ulonglong2*)(sm + SAV + (n8 * 3 + i) * 20),
                        wvp, q8, b0, b1);
                hv[i][0] = fold2(b0);
                hv[i][1] = fold2(b1);
            }
            float4* v4p = (float4*)(sm + SV4);
            #pragma unroll
            for (int k = 0; k < 2; ++k) {
                float4 vv = v4p[n8 * 17 + q8 * 2 + k];
                vv.x += fmaxf(hv[0][k], 0.f);
                vv.y += fmaxf(hv[1][k], 0.f);
                vv.z += fmaxf(hv[2][k], 0.f);
                v4p[n8 * 17 + q8 * 2 + k] = vv;
            }
        }
        __syncthreads();
    }

    // ---- pool ----
    if (tid < 80) {
        float acc = 0.f;
        if (tid < 32) {
            #pragma unroll
            for (int n = 0; n < 32; ++n) acc += sm[SS + n * 36 + tid];
        } else {
            int j = tid - 32;
            int w = j / 3, c = j - w * 3;
            #pragma unroll
            for (int n = 0; n < 32; ++n) acc += sm[SV4 + (n * 17 + w) * 4 + c];
        }
        g_hg[g * 80 + tid] = acc;
    }
}

// ---------------------------------------------------------------------------
// readout MLP (unchanged from v8): 16 graphs/CTA, single wave, cp.async
// double commit groups, H aliases the dead W1 buffer, packed f32x2 math.
// ---------------------------------------------------------------------------
#define MW1  0        // 20480 (W1; H [16][256] aliases after phase 1)
#define MH   0
#define MW2  20480    // 32768
#define MA   53248    // 1280 [g][80]
#define MB1  54528    // 256
#define MB2  54784    // 128
#define SMEM_MLP (54912 * 4)

__global__ void __launch_bounds__(256, 1) k_mlp(
    const float* __restrict__ Wr1, const float* __restrict__ br1,
    const float* __restrict__ Wr2, const float* __restrict__ br2,
    float* __restrict__ out, int B)
{
    extern __shared__ float sm[];
    const int tid = threadIdx.x;
    const int g0  = blockIdx.x * 16;

    // group 1: W1 + A + biases
    {
        float4* w1d = (float4*)(sm + MW1);
        const float4* w1s = (const float4*)Wr1;
        #pragma unroll
        for (int i = 0; i < 20; ++i)
            cpa16(w1d + tid + 256 * i, w1s + tid + 256 * i);
        for (int idx = tid; idx < 320; idx += 256) {
            int gg = idx / 20, c = idx % 20;
            if (g0 + gg < B)
                cpa16((float4*)(sm + MA + gg * 80) + c,
                      (const float4*)(g_hg + (size_t)(g0 + gg) * 80) + c);
        }
        if (tid < 64)  cpa16((float4*)(sm + MB1) + tid, (const float4*)br1 + tid);
        if (tid < 32)  cpa16((float4*)(sm + MB2) + tid, (const float4*)br2 + tid);
        cpa_commit();
    }
    // group 2: W2
    {
        float4* w2d = (float4*)(sm + MW2);
        const float4* w2s = (const float4*)Wr2;
        #pragma unroll
        for (int i = 0; i < 32; ++i)
            cpa16(w2d + tid + 256 * i, w2s + tid + 256 * i);
        cpa_commit();
    }

    cpa_wait<1>();           // W1 + A ready (W2 still in flight)
    __syncthreads();

    // phase 1 -> registers: 4 graphs x 4 outputs per thread, packed
    const int gq = tid >> 6;
    const int oq = tid & 63;
    u64 c01[4], c23[4];
    #pragma unroll
    for (int gi = 0; gi < 4; ++gi) { c01[gi] = 0; c23[gi] = 0; }
    {
        const ulonglong2* w4p = (const ulonglong2*)(sm + MW1);
        #pragma unroll 4
        for (int k = 0; k < 80; ++k) {
            ulonglong2 w = w4p[k * 64 + oq];
            #pragma unroll
            for (int gi = 0; gi < 4; ++gi) {
                u64 a2 = splat2(sm[MA + (4 * gq + gi) * 80 + k]);
                ffma2(c01[gi], a2, w.x);
                ffma2(c23[gi], a2, w.y);
            }
        }
    }
    float4 b4 = ((const float4*)(sm + MB1))[oq];
    __syncthreads();         // all W1 reads done before H overwrites it

    {
        float4* h4p = (float4*)(sm + MH);
        #pragma unroll
        for (int gi = 0; gi < 4; ++gi) {
            float x0, x1, x2, x3;
            upk2(c01[gi], x0, x1); upk2(c23[gi], x2, x3);
            float4 hv;
            hv.x = fmaxf(x0 + b4.x, 0.f);
            hv.y = fmaxf(x1 + b4.y, 0.f);
            hv.z = fmaxf(x2 + b4.z, 0.f);
            hv.w = fmaxf(x3 + b4.w, 0.f);
            h4p[(4 * gq + gi) * 64 + oq] = hv;
        }
    }
    cpa_wait<0>();           // W2 ready
    __syncthreads();

    // phase 2: 2 graphs x 4 outputs per thread, packed
    {
        const int g2 = tid >> 5;
        const int o2 = tid & 31;
        u64 d0a = 0, d0b = 0, d1a = 0, d1b = 0;
        const ulonglong2* w4p = (const ulonglong2*)(sm + MW2);
        const float* h0 = sm + MH + (2 * g2) * 256;
        const float* h1 = sm + MH + (2 * g2 + 1) * 256;
        #pragma unroll 4
        for (int k = 0; k < 256; ++k) {
            u64 a0 = splat2(h0[k]);
            u64 a1 = splat2(h1[k]);
            ulonglong2 w = w4p[k * 32 + o2];
            ffma2(d0a, a0, w.x); ffma2(d0b, a0, w.y);
            ffma2(d1a, a1, w.x); ffma2(d1b, a1, w.y);
        }
        float4 bb = ((const float4*)(sm + MB2))[o2];
        int ga = g0 + 2 * g2, gb = ga + 1;
        float e0, e1, e2, e3;
        if (ga < B) {
            upk2(d0a, e0, e1); upk2(d0b, e2, e3);
            float4 o; o.x = e0 + bb.x; o.y = e1 + bb.y;
            o.z = e2 + bb.z; o.w = e3 + bb.w;
            ((float4*)(out + (size_t)ga * 128))[o2] = o;
        }
        if (gb < B) {
            upk2(d1a, e0, e1); upk2(d1b, e2, e3);
            float4 o; o.x = e0 + bb.x; o.y = e1 + bb.y;
            o.z = e2 + bb.z; o.w = e3 + bb.w;
            ((float4*)(out + (size_t)gb * 128))[o2] = o;
        }
    }
}

extern "C" void kernel_launch(void* const* d_in, const int* in_sizes, int n_in,
                              void* d_out, int out_size)
{
    int ie = -1;
    for (int i = 0; i < n_in; ++i)
        if (in_sizes[i] == 3200) { ie = i; break; }
    if (ie < 0) return;

    const float* pos = (const float*)d_in[0];
    int N = in_sizes[0] / 3;
    int B = N / 32;

    const float* emb  = (const float*)d_in[ie];
    const float* Ws2n = (const float*)d_in[ie + 1];
    const float* W1   = (const float*)d_in[ie + 2];
    const float* W2   = (const float*)d_in[ie + 3];
    const float* W3   = (const float*)d_in[ie + 4];
    const float* W4   = (const float*)d_in[ie + 5];
    const float* Ws   = (const float*)d_in[ie + 6];
    const float* Wv   = (const float*)d_in[ie + 7];
    const float* Wr1  = (const float*)d_in[ie + 8];
    const float* br1  = (const float*)d_in[ie + 9];
    const float* Wr2  = (const float*)d_in[ie + 10];
    const float* br2  = (const float*)d_in[ie + 11];

    const int* z = nullptr;
    for (int i = 1; i < n_in; ++i) {
        if (i >= ie && i <= ie + 11) continue;
        if (in_sizes[i] == N) { z = (const int*)d_in[i]; break; }  // z precedes batch
    }
    if (!z || B > MAXB || N > MAXN) return;

    cudaFuncSetAttribute((const void*)k_gnn,
                         cudaFuncAttributeMaxDynamicSharedMemorySize, SMEM_GNN);
    cudaFuncSetAttribute((const void*)k_mlp,
                         cudaFuncAttributeMaxDynamicSharedMemorySize, SMEM_MLP);

    k_pack<<<(PACKN + 255) / 256, 256>>>(Ws2n, W1, W2, W3, W4, Ws, Wv);
    k_gnn<<<B, 256, SMEM_GNN>>>(pos, z, emb);
    k_mlp<<<(B + 15) / 16, 256, SMEM_MLP>>>(Wr1, br1, Wr2, br2, (float*)d_out, B);
}

// round 16
// speedup vs baseline: 2.1513x; 2.1513x over previous
#include <cuda_runtime.h>

// ---------------------------------------------------------------------------
// EquivGNNEncoder on GB300, v12 = v8 + dual-chain interleaved edge gather.
// Gather was latency-bound (serial per-node neighbor loops of dependent
// LDS->rsqrt->FMA chains); nodes are now processed as 2 independent
// interleaved chains per warp so latency overlaps and trip count is
// max(popcount) not sum. All dense phases identical to v8 (201.8us best).
// ---------------------------------------------------------------------------

#define MAXN (1 << 17)
#define MAXB 4096

typedef unsigned long long u64;

__device__ float g_hg[MAXB * 80];

__device__ __forceinline__ void cpa16(void* s, const void* g) {
    unsigned sa = (unsigned)__cvta_generic_to_shared(s);
    asm volatile("cp.async.cg.shared.global [%0], [%1], 16;\n" :: "r"(sa), "l"(g));
}
__device__ __forceinline__ void cpa_commit() {
    asm volatile("cp.async.commit_group;\n");
}
template<int N> __device__ __forceinline__ void cpa_wait() {
    asm volatile("cp.async.wait_group %0;\n" :: "n"(N) : "memory");
}

__device__ __forceinline__ u64 pk2(float lo, float hi) {
    u64 r; asm("mov.b64 %0, {%1, %2};" : "=l"(r) : "f"(lo), "f"(hi)); return r;
}
__device__ __forceinline__ u64 splat2(float v) { return pk2(v, v); }
__device__ __forceinline__ void upk2(u64 v, float& lo, float& hi) {
    asm("mov.b64 {%0, %1}, %2;" : "=f"(lo), "=f"(hi) : "l"(v));
}
__device__ __forceinline__ void ffma2(u64& d, u64 a, u64 b) {
    asm("fma.rn.f32x2 %0, %1, %2, %0;" : "+l"(d) : "l"(a), "l"(b));
}
__device__ __forceinline__ void fadd2(u64& d, u64 a) {
    asm("add.rn.f32x2 %0, %1, %0;" : "+l"(d) : "l"(a));
}

// smem float offsets (total 14272 floats = 57088 B -> 4 CTAs/SM):
#define SPOS 0        // pos float4 [32]        (128)
#define SS   128      // [n] stride 36          (1152)
#define SV4  1280     // float4 [n*17+w]        (2176)
#define SSB  3456     // S_bar [n] stride 36    (1152)
#define SR   4608     // r [n] stride 20        (640)
#define SVB  5248     // Vbar [(n*3+i)]*20      (1920)
#define SP   7168     // p [(n*3+i)]*36         (3456)
#define SAS  7168     // alias over sP          (1152)
#define SAV  8320     // alias over sP          (1920)
#define SW   10624    // 3584: [W1 0|W2 1024|W3 1536|W4 1792|Ws 2304|Wv 3328]
#define SADJ 14208
#define SZI  14240
#define SMEM_GNN (14272 * 4)

__global__ void __launch_bounds__(256, 4) k_gnn(
    const float* __restrict__ pos, const int* __restrict__ z,
    const float* __restrict__ emb, const float* __restrict__ Ws2n,
    const float* __restrict__ W1g, const float* __restrict__ W2g,
    const float* __restrict__ W3g, const float* __restrict__ W4g,
    const float* __restrict__ Wsg, const float* __restrict__ Wvg)
{
    extern __shared__ float sm[];
    float* sW = sm + SW;
    unsigned* sAdj = (unsigned*)(sm + SADJ);
    int*      sZi  = (int*)(sm + SZI);

    const int g    = blockIdx.x;
    const int tid  = threadIdx.x;
    const int n8   = tid >> 3;     // node (0..31)
    const int q8   = tid & 7;      // slice
    const int warp = tid >> 5;
    const int lane = tid & 31;

    const float SQRT3    = 1.7320508075688772f;
    const float INVS3    = 0.5773502691896258f;
    const float C_S      = 0.14433756729740643f;  // 1/sqrt(48)
    const float C_VI     = 0.14433756729740643f;
    const float INV_SQ32 = 0.17677669529663687f;
    const float R2       = 25.0f;

    // ---- stage Ws2n via cp.async; load statics ----
    cpa16((float4*)sW + tid, (const float4*)Ws2n + tid);
    cpa_commit();
    if (tid < 96) {
        int n = tid / 3, c = tid - n * 3;
        sm[SPOS + n * 4 + c] = pos[g * 96 + tid];
    }
    if (tid < 32) {
        sm[SPOS + tid * 4 + 3] = 0.f;
        sZi[tid] = z[g * 32 + tid];
    }
    __syncthreads();

    // ---- adjacency from pos (bit-identical to reference predicate) ----
    {
        const float4* pos4 = (const float4*)(sm + SPOS);
        float4 pm = pos4[lane];
        #pragma unroll
        for (int k = 0; k < 4; ++k) {
            int n = warp * 4 + k;
            float4 pn = pos4[n];
            float dx = __fsub_rn(pn.x, pm.x);
            float dy = __fsub_rn(pn.y, pm.y);
            float dz = __fsub_rn(pn.z, pm.z);
            float d2 = __fadd_rn(__fadd_rn(__fmul_rn(dx, dx), __fmul_rn(dy, dy)),
                                 __fmul_rn(dz, dz));
            unsigned msk = __ballot_sync(0xffffffffu, d2 <= R2 && d2 > 0.f);
            if (lane == 0) sAdj[n] = msk;
        }
    }

    // ---- emb gather, v = 0 ----
    {
        const float4* emb4 = (const float4*)emb;
        ((float4*)(sm + SSB + n8 * 36))[q8] = emb4[sZi[n8] * 8 + q8];
        float4 z4 = {0.f, 0.f, 0.f, 0.f};
        for (int i = tid; i < 544; i += 256) ((float4*)(sm + SV4))[i] = z4;
    }
    cpa_wait<0>();
    __syncthreads();

    // ---- initial s = (emb @ Ws2n)/sqrt(32), packed ----
    {
        u64 a01 = 0, a23 = 0;
        const float4* inf = (const float4*)(sm + SSB + n8 * 36);
        const ulonglong2* wf = (const ulonglong2*)sW;
        #pragma unroll
        for (int u4 = 0; u4 < 8; ++u4) {
            float4 s4 = inf[u4];
            float sv[4] = {s4.x, s4.y, s4.z, s4.w};
            #pragma unroll
            for (int j = 0; j < 4; ++j) {
                u64 sj = splat2(sv[j]);
                ulonglong2 w = wf[(u4 * 4 + j) * 8 + q8];
                ffma2(a01, sj, w.x);
                ffma2(a23, sj, w.y);
            }
        }
        float a0, a1, a2, a3;
        upk2(a01, a0, a1); upk2(a23, a2, a3);
        float4 o;
        o.x = a0 * INV_SQ32; o.y = a1 * INV_SQ32;
        o.z = a2 * INV_SQ32; o.w = a3 * INV_SQ32;
        ((float4*)(sm + SS + n8 * 36))[q8] = o;
    }
    __syncthreads();

    // ---- layers ----
    for (int l = 0; l < 3; ++l) {
        // stage layer weights directly from the 6 arrays (overlaps gather)
        {
            float4* wd = (float4*)sW;
            cpa16(wd + tid,        (const float4*)W1g + l * 256 + tid);        // W1
            cpa16(wd + 576 + tid,  (const float4*)Wsg + l * 256 + tid);        // Ws
            if (tid < 128)
                cpa16(wd + 256 + tid, (const float4*)W2g + l * 128 + tid);     // W2
            else
                cpa16(wd + 448 + (tid - 128),
                      (const float4*)W4g + l * 128 + (tid - 128));             // W4
            if (tid < 64)
                cpa16(wd + 384 + tid, (const float4*)W3g + l * 64 + tid);      // W3
            else if (tid < 128)
                cpa16(wd + 832 + (tid - 64),
                      (const float4*)Wvg + l * 64 + (tid - 64));               // Wv
            cpa_commit();
        }

        // ---- edge gather: 2 interleaved node chains per pass ----
        {
            int w2 = lane & 15;
            const float4* v4p = (const float4*)(sm + SV4);
            const float4* pos4 = (const float4*)(sm + SPOS);
            #pragma unroll
            for (int p = 0; p < 2; ++p) {
                int na = warp * 4 + 2 * p;
                int nb = na + 1;
                float4 pa = pos4[na];
                float4 pb = pos4[nb];
                unsigned ma = sAdj[na];
                unsigned mb = sAdj[nb];
                float aS_a = 0.f, aPz_a = 0.f, aVz_a = 0.f, aRz_a = 0.f;
                float aS_b = 0.f, aPz_b = 0.f, aVz_b = 0.f, aRz_b = 0.f;
                u64 aPxy_a = 0, aVxy_a = 0, aRxy_a = 0;
                u64 aPxy_b = 0, aVxy_b = 0, aRxy_b = 0;
                while (ma | mb) {
                    if (ma) {
                        int m = __ffs(ma) - 1;
                        ma &= ma - 1;
                        float4 pm = pos4[m];
                        float dx = pa.x - pm.x;
                        float dy = pa.y - pm.y;
                        float dz = pa.z - pm.z;
                        float iv = SQRT3 * rsqrtf(dx * dx + dy * dy + dz * dz);
                        float sx = dx * iv, sy = dy * iv, sz = dz * iv;
                        u64 sxy = pk2(sx, sy);
                        float su = sm[SS + m * 36 + lane];
                        aS_a += su;
                        ffma2(aPxy_a, splat2(su), sxy);
                        aPz_a = fmaf(su, sz, aPz_a);
                        ulonglong2 vv = *(const ulonglong2*)(v4p + m * 17 + w2);
                        fadd2(aVxy_a, vv.x);
                        float vz, vpad;
                        upk2(vv.y, vz, vpad);
                        aVz_a += vz;
                        ffma2(aRxy_a, vv.x, sxy);
                        aRz_a = fmaf(vz, sz, aRz_a);
                    }
                    if (mb) {
                        int m = __ffs(mb) - 1;
                        mb &= mb - 1;
                        float4 pm = pos4[m];
                        float dx = pb.x - pm.x;
                        float dy = pb.y - pm.y;
                        float dz = pb.z - pm.z;
                        float iv = SQRT3 * rsqrtf(dx * dx + dy * dy + dz * dz);
                        float sx = dx * iv, sy = dy * iv, sz = dz * iv;
                        u64 sxy = pk2(sx, sy);
                        float su = sm[SS + m * 36 + lane];
                        aS_b += su;
                        ffma2(aPxy_b, splat2(su), sxy);
                        aPz_b = fmaf(su, sz, aPz_b);
                        ulonglong2 vv = *(const ulonglong2*)(v4p + m * 17 + w2);
                        fadd2(aVxy_b, vv.x);
                        float vz, vpad;
                        upk2(vv.y, vz, vpad);
                        aVz_b += vz;
                        ffma2(aRxy_b, vv.x, sxy);
                        aRz_b = fmaf(vz, sz, aRz_b);
                    }
                }
                float px, py, vxs, vys, rx, ry;
                upk2(aPxy_a, px, py);
                upk2(aVxy_a, vxs, vys);
                upk2(aRxy_a, rx, ry);
                sm[SSB + na * 36 + lane] = aS_a;
                sm[SP + (na * 3 + 0) * 36 + lane] = px;
                sm[SP + (na * 3 + 1) * 36 + lane] = py;
                sm[SP + (na * 3 + 2) * 36 + lane] = aPz_a;
                if (lane < 16) {
                    sm[SVB + (na * 3 + 0) * 20 + lane] = vxs;
                    sm[SVB + (na * 3 + 1) * 20 + lane] = vys;
                    sm[SVB + (na * 3 + 2) * 20 + lane] = aVz_a;
                    sm[SR + na * 20 + lane] = (rx + ry) + aRz_a;
                }
                upk2(aPxy_b, px, py);
                upk2(aVxy_b, vxs, vys);
                upk2(aRxy_b, rx, ry);
                sm[SSB + nb * 36 + lane] = aS_b;
                sm[SP + (nb * 3 + 0) * 36 + lane] = px;
                sm[SP + (nb * 3 + 1) * 36 + lane] = py;
                sm[SP + (nb * 3 + 2) * 36 + lane] = aPz_b;
                if (lane < 16) {
                    sm[SVB + (nb * 3 + 0) * 20 + lane] = vxs;
                    sm[SVB + (nb * 3 + 1) * 20 + lane] = vys;
                    sm[SVB + (nb * 3 + 2) * 20 + lane] = aVz_b;
                    sm[SR + nb * 20 + lane] = (rx + ry) + aRz_b;
                }
            }
        }
        cpa_wait<0>();
        __syncthreads();

        // ---- step A part 1: a_v_i = C_VI*(p_i@W2 + Vbar_i@W3), packed ----
        float avv[3][2];
        {
            const u64* w2u = (const u64*)(sW + 1024);
            const u64* w3u = (const u64*)(sW + 1536);
            #pragma unroll
            for (int i = 0; i < 3; ++i) {
                u64 acc = 0;
                const float4* pf = (const float4*)(sm + SP + (n8 * 3 + i) * 36);
                #pragma unroll
                for (int u4 = 0; u4 < 8; ++u4) {
                    float4 p4 = pf[u4];
                    float pv[4] = {p4.x, p4.y, p4.z, p4.w};
                    #pragma unroll
                    for (int j = 0; j < 4; ++j)
                        ffma2(acc, splat2(pv[j]), w2u[(u4 * 4 + j) * 8 + q8]);
                }
                const float4* vbf = (const float4*)(sm + SVB + (n8 * 3 + i) * 20);
                #pragma unroll
                for (int u4 = 0; u4 < 4; ++u4) {
                    float4 v4 = vbf[u4];
                    float vval[4] = {v4.x, v4.y, v4.z, v4.w};
                    #pragma unroll
                    for (int j = 0; j < 4; ++j)
                        ffma2(acc, splat2(vval[j]), w3u[(u4 * 4 + j) * 8 + q8]);
                }
                float a0, a1;
                upk2(acc, a0, a1);
                avv[i][0] = C_VI * a0;
                avv[i][1] = C_VI * a1;
            }
        }
        __syncthreads();   // all sP/sVb reads done; aliased region writable

        // step A part 2: write a_v; a_s = C_S*(Sbar@W1 + INVS3*r@W4) -> SAS
        {
            #pragma unroll
            for (int i = 0; i < 3; ++i)
                *(float2*)(sm + SAV + (n8 * 3 + i) * 20 + q8 * 2) =
                    make_float2(avv[i][0], avv[i][1]);

            u64 a01 = 0, a23 = 0;
            {
                const float4* inf = (const float4*)(sm + SSB + n8 * 36);
                const ulonglong2* wf = (const ulonglong2*)sW;
                #pragma unroll
                for (int u4 = 0; u4 < 8; ++u4) {
                    float4 s4 = inf[u4];
                    float sv[4] = {s4.x, s4.y, s4.z, s4.w};
                    #pragma unroll
                    for (int j = 0; j < 4; ++j) {
                        u64 sj = splat2(sv[j]);
                        ulonglong2 w = wf[(u4 * 4 + j) * 8 + q8];
                        ffma2(a01, sj, w.x);
                        ffma2(a23, sj, w.y);
                    }
                }
            }
            {
                const float4* inf = (const float4*)(sm + SR + n8 * 20);
                const ulonglong2* wf = (const ulonglong2*)(sW + 1792);
                #pragma unroll
                for (int u4 = 0; u4 < 4; ++u4) {
                    float4 r4 = inf[u4];
                    float rv[4] = {r4.x, r4.y, r4.z, r4.w};
                    #pragma unroll
                    for (int j = 0; j < 4; ++j) {
                        u64 rj = splat2(rv[j] * INVS3);
                        ulonglong2 w = wf[(u4 * 4 + j) * 8 + q8];
                        ffma2(a01, rj, w.x);
                        ffma2(a23, rj, w.y);
                    }
                }
            }
            float a0, a1, a2, a3;
            upk2(a01, a0, a1); upk2(a23, a2, a3);
            float4 o;
            o.x = C_S * a0; o.y = C_S * a1;
            o.z = C_S * a2; o.w = C_S * a3;
            ((float4*)(sm + SAS + n8 * 36))[q8] = o;
        }
        __syncthreads();

        // ---- step B: s += relu((a_s@Ws)/sqrt32); v_i += relu((a_v_i@Wv)/4) ----
        {
            u64 a01 = 0, a23 = 0;
            const float4* inf = (const float4*)(sm + SAS + n8 * 36);
            const ulonglong2* wf = (const ulonglong2*)(sW + 2304);
            #pragma unroll
            for (int u4 = 0; u4 < 8; ++u4) {
                float4 a4 = inf[u4];
                float av_[4] = {a4.x, a4.y, a4.z, a4.w};
                #pragma unroll
                for (int j = 0; j < 4; ++j) {
                    u64 aj = splat2(av_[j]);
                    ulonglong2 w = wf[(u4 * 4 + j) * 8 + q8];
                    ffma2(a01, aj, w.x);
                    ffma2(a23, aj, w.y);
                }
            }
            float a0, a1, a2, a3;
            upk2(a01, a0, a1); upk2(a23, a2, a3);
            float4* sp = (float4*)(sm + SS + n8 * 36) + q8;
            float4 sv = *sp;
            sv.x += fmaxf(a0 * INV_SQ32, 0.f);
            sv.y += fmaxf(a1 * INV_SQ32, 0.f);
            sv.z += fmaxf(a2 * INV_SQ32, 0.f);
            sv.w += fmaxf(a3 * INV_SQ32, 0.f);
            *sp = sv;

            float hv[3][2];
            const u64* wvu = (const u64*)(sW + 3328);
            #pragma unroll
            for (int i = 0; i < 3; ++i) {
                u64 acc = 0;
                const float4* af = (const float4*)(sm + SAV + (n8 * 3 + i) * 20);
                #pragma unroll
                for (int u4 = 0; u4 < 4; ++u4) {
                    float4 a4 = af[u4];
                    float av_[4] = {a4.x, a4.y, a4.z, a4.w};
                    #pragma unroll
                    for (int j = 0; j < 4; ++j)
                        ffma2(acc, splat2(av_[j]), wvu[(u4 * 4 + j) * 8 + q8]);
                }
                upk2(acc, hv[i][0], hv[i][1]);
            }
            float4* v4p = (float4*)(sm + SV4);
            #pragma unroll
            for (int k = 0; k < 2; ++k) {
                float4 vv = v4p[n8 * 17 + q8 * 2 + k];
                vv.x += fmaxf(hv[0][k] * 0.25f, 0.f);
                vv.y += fmaxf(hv[1][k] * 0.25f, 0.f);
                vv.z += fmaxf(hv[2][k] * 0.25f, 0.f);
                v4p[n8 * 17 + q8 * 2 + k] = vv;
            }
        }
        __syncthreads();
    }

    // ---- pool ----
    if (tid < 80) {
        float acc = 0.f;
        if (tid < 32) {
            #pragma unroll
            for (int n = 0; n < 32; ++n) acc += sm[SS + n * 36 + tid];
        } else {
            int j = tid - 32;
            int w = j / 3, c = j - w * 3;
            #pragma unroll
            for (int n = 0; n < 32; ++n) acc += sm[SV4 + (n * 17 + w) * 4 + c];
        }
        g_hg[g * 80 + tid] = acc;
    }
}

// ---------------------------------------------------------------------------
// readout MLP (unchanged from v8): 16 graphs/CTA, single wave, cp.async
// double commit groups, H aliases the dead W1 buffer, packed f32x2 math.
// ---------------------------------------------------------------------------
#define MW1  0        // 20480 (W1; H [16][256] aliases after phase 1)
#define MH   0
#define MW2  20480    // 32768
#define MA   53248    // 1280 [g][80]
#define MB1  54528    // 256
#define MB2  54784    // 128
#define SMEM_MLP (54912 * 4)

__global__ void __launch_bounds__(256, 1) k_mlp(
    const float* __restrict__ Wr1, const float* __restrict__ br1,
    const float* __restrict__ Wr2, const float* __restrict__ br2,
    float* __restrict__ out, int B)
{
    extern __shared__ float sm[];
    const int tid = threadIdx.x;
    const int g0  = blockIdx.x * 16;

    // group 1: W1 + A + biases
    {
        float4* w1d = (float4*)(sm + MW1);
        const float4* w1s = (const float4*)Wr1;
        #pragma unroll
        for (int i = 0; i < 20; ++i)
            cpa16(w1d + tid + 256 * i, w1s + tid + 256 * i);
        for (int idx = tid; idx < 320; idx += 256) {
            int gg = idx / 20, c = idx % 20;
            if (g0 + gg < B)
                cpa16((float4*)(sm + MA + gg * 80) + c,
                      (const float4*)(g_hg + (size_t)(g0 + gg) * 80) + c);
        }
        if (tid < 64)  cpa16((float4*)(sm + MB1) + tid, (const float4*)br1 + tid);
        if (tid < 32)  cpa16((float4*)(sm + MB2) + tid, (const float4*)br2 + tid);
        cpa_commit();
    }
    // group 2: W2
    {
        float4* w2d = (float4*)(sm + MW2);
        const float4* w2s = (const float4*)Wr2;
        #pragma unroll
        for (int i = 0; i < 32; ++i)
            cpa16(w2d + tid + 256 * i, w2s + tid + 256 * i);
        cpa_commit();
    }

    cpa_wait<1>();           // W1 + A ready (W2 still in flight)
    __syncthreads();

    // phase 1 -> registers: 4 graphs x 4 outputs per thread, packed
    const int gq = tid >> 6;
    const int oq = tid & 63;
    u64 c01[4], c23[4];
    #pragma unroll
    for (int gi = 0; gi < 4; ++gi) { c01[gi] = 0; c23[gi] = 0; }
    {
        const ulonglong2* w4p = (const ulonglong2*)(sm + MW1);
        #pragma unroll 4
        for (int k = 0; k < 80; ++k) {
            ulonglong2 w = w4p[k * 64 + oq];
            #pragma unroll
            for (int gi = 0; gi < 4; ++gi) {
                u64 a2 = splat2(sm[MA + (4 * gq + gi) * 80 + k]);
                ffma2(c01[gi], a2, w.x);
                ffma2(c23[gi], a2, w.y);
            }
        }
    }
    float4 b4 = ((const float4*)(sm + MB1))[oq];
    __syncthreads();         // all W1 reads done before H overwrites it

    {
        float4* h4p = (float4*)(sm + MH);
        #pragma unroll
        for (int gi = 0; gi < 4; ++gi) {
            float x0, x1, x2, x3;
            upk2(c01[gi], x0, x1); upk2(c23[gi], x2, x3);
            float4 hv;
            hv.x = fmaxf(x0 + b4.x, 0.f);
            hv.y = fmaxf(x1 + b4.y, 0.f);
            hv.z = fmaxf(x2 + b4.z, 0.f);
            hv.w = fmaxf(x3 + b4.w, 0.f);
            h4p[(4 * gq + gi) * 64 + oq] = hv;
        }
    }
    cpa_wait<0>();           // W2 ready
    __syncthreads();

    // phase 2: 2 graphs x 4 outputs per thread, packed
    {
        const int g2 = tid >> 5;
        const int o2 = tid & 31;
        u64 d0a = 0, d0b = 0, d1a = 0, d1b = 0;
        const ulonglong2* w4p = (const ulonglong2*)(sm + MW2);
        const float* h0 = sm + MH + (2 * g2) * 256;
        const float* h1 = sm + MH + (2 * g2 + 1) * 256;
        #pragma unroll 4
        for (int k = 0; k < 256; ++k) {
            u64 a0 = splat2(h0[k]);
            u64 a1 = splat2(h1[k]);
            ulonglong2 w = w4p[k * 32 + o2];
            ffma2(d0a, a0, w.x); ffma2(d0b, a0, w.y);
            ffma2(d1a, a1, w.x); ffma2(d1b, a1, w.y);
        }
        float4 bb = ((const float4*)(sm + MB2))[o2];
        int ga = g0 + 2 * g2, gb = ga + 1;
        float e0, e1, e2, e3;
        if (ga < B) {
            upk2(d0a, e0, e1); upk2(d0b, e2, e3);
            float4 o; o.x = e0 + bb.x; o.y = e1 + bb.y;
            o.z = e2 + bb.z; o.w = e3 + bb.w;
            ((float4*)(out + (size_t)ga * 128))[o2] = o;
        }
        if (gb < B) {
            upk2(d1a, e0, e1); upk2(d1b, e2, e3);
            float4 o; o.x = e0 + bb.x; o.y = e1 + bb.y;
            o.z = e2 + bb.z; o.w = e3 + bb.w;
            ((float4*)(out + (size_t)gb * 128))[o2] = o;
        }
    }
}

extern "C" void kernel_launch(void* const* d_in, const int* in_sizes, int n_in,
                              void* d_out, int out_size)
{
    int ie = -1;
    for (int i = 0; i < n_in; ++i)
        if (in_sizes[i] == 3200) { ie = i; break; }
    if (ie < 0) return;

    const float* pos = (const float*)d_in[0];
    int N = in_sizes[0] / 3;
    int B = N / 32;

    const float* emb  = (const float*)d_in[ie];
    const float* Ws2n = (const float*)d_in[ie + 1];
    const float* W1   = (const float*)d_in[ie + 2];
    const float* W2   = (const float*)d_in[ie + 3];
    const float* W3   = (const float*)d_in[ie + 4];
    const float* W4   = (const float*)d_in[ie + 5];
    const float* Ws   = (const float*)d_in[ie + 6];
    const float* Wv   = (const float*)d_in[ie + 7];
    const float* Wr1  = (const float*)d_in[ie + 8];
    const float* br1  = (const float*)d_in[ie + 9];
    const float* Wr2  = (const float*)d_in[ie + 10];
    const float* br2  = (const float*)d_in[ie + 11];

    const int* z = nullptr;
    for (int i = 1; i < n_in; ++i) {
        if (i >= ie && i <= ie + 11) continue;
        if (in_sizes[i] == N) { z = (const int*)d_in[i]; break; }  // z precedes batch
    }
    if (!z || B > MAXB || N > MAXN) return;

    cudaFuncSetAttribute((const void*)k_gnn,
                         cudaFuncAttributeMaxDynamicSharedMemorySize, SMEM_GNN);
    cudaFuncSetAttribute((const void*)k_mlp,
                         cudaFuncAttributeMaxDynamicSharedMemorySize, SMEM_MLP);

    k_gnn<<<B, 256, SMEM_GNN>>>(pos, z, emb, Ws2n, W1, W2, W3, W4, Ws, Wv);
    k_mlp<<<(B + 15) / 16, 256, SMEM_MLP>>>(Wr1, br1, Wr2, br2, (float*)d_out, B);
}